// round 3
// baseline (speedup 1.0000x reference)
#include <cuda_runtime.h>

// 2x2 Haar inverse reconstruction:
//   x: (32, 4, 512, 512) f32  ->  out: (32, 1, 1024, 1024) f32
// With a,b,c,d = x[n,0..3,h,w]:
//   L0 = R*a + R*b ; L1 = R*a - R*b
//   H0 = R*c + R*d ; H1 = R*c - R*d
//   out[n,2h,  2w] = R*L0 + R*H0 ; out[n,2h,  2w+1] = R*L0 - R*H0
//   out[n,2h+1,2w] = R*L1 + R*H1 ; out[n,2h+1,2w+1] = R*L1 - R*H1
//
// Streaming kernel: 128MiB in + 128MiB out, all touch-once -> use .cs hints.
// Each thread: 8 floats per channel (8x LDG.128 .cs), emits 16 floats to each
// of two output rows (8x STG.128 .cs). MLP_p1 = 8.

#define RCONST 0.70710678118654752440f

static constexpr int S = 512;     // input spatial
static constexpr int NIMG = 32;   // batch
static constexpr int WO = S / 8;  // 8-float chunks per row = 64

__device__ __forceinline__ void haar4(float a, float b, float c, float d,
                                      float& o00, float& o01, float& o10, float& o11) {
    float l0 = RCONST * a + RCONST * b;
    float l1 = RCONST * a - RCONST * b;
    float h0 = RCONST * c + RCONST * d;
    float h1 = RCONST * c - RCONST * d;
    o00 = RCONST * l0 + RCONST * h0;
    o01 = RCONST * l0 - RCONST * h0;
    o10 = RCONST * l1 + RCONST * h1;
    o11 = RCONST * l1 - RCONST * h1;
}

// process one float4 group (a,b,c,d) -> two float4s for row0, two for row1
__device__ __forceinline__ void haar_vec(const float4& a, const float4& b,
                                         const float4& c, const float4& d,
                                         float4& r0lo, float4& r0hi,
                                         float4& r1lo, float4& r1hi) {
    haar4(a.x, b.x, c.x, d.x, r0lo.x, r0lo.y, r1lo.x, r1lo.y);
    haar4(a.y, b.y, c.y, d.y, r0lo.z, r0lo.w, r1lo.z, r1lo.w);
    haar4(a.z, b.z, c.z, d.z, r0hi.x, r0hi.y, r1hi.x, r1hi.y);
    haar4(a.w, b.w, c.w, d.w, r0hi.z, r0hi.w, r1hi.z, r1hi.w);
}

__global__ __launch_bounds__(256)
void haar_recon_kernel(const float* __restrict__ x, float* __restrict__ out) {
    // tid layout: [n:5][h:9][wo:6]   total = 32*512*64 = 1,048,576 threads
    unsigned tid = blockIdx.x * 256u + threadIdx.x;
    unsigned wo = tid & (WO - 1);
    unsigned h  = (tid >> 6) & (S - 1);
    unsigned n  = tid >> 15;

    const size_t cs4 = (size_t)S * S / 4;   // channel stride in float4 units
    const float4* base = (const float4*)(x + (size_t)n * 4 * S * S + (size_t)h * S) + 2 * wo;

    // 8 independent 128-bit streaming loads, issued back-to-back (MLP=8)
    float4 a0 = __ldcs(base + 0);
    float4 a1 = __ldcs(base + 1);
    float4 b0 = __ldcs(base + cs4);
    float4 b1 = __ldcs(base + cs4 + 1);
    float4 c0 = __ldcs(base + 2 * cs4);
    float4 c1 = __ldcs(base + 2 * cs4 + 1);
    float4 d0 = __ldcs(base + 3 * cs4);
    float4 d1 = __ldcs(base + 3 * cs4 + 1);

    float4 r0[4], r1[4];  // row 2h: 16 floats; row 2h+1: 16 floats
    haar_vec(a0, b0, c0, d0, r0[0], r0[1], r1[0], r1[1]);
    haar_vec(a1, b1, c1, d1, r0[2], r0[3], r1[2], r1[3]);

    // output: (n, 2S, 2S); rows 2h and 2h+1, cols [16*wo, 16*wo+16)
    float4* orow0 = (float4*)(out + ((size_t)n * 2 * S + 2 * h) * (2 * S)) + 4 * wo;
    float4* orow1 = orow0 + (2 * S) / 4;

    __stcs(orow0 + 0, r0[0]);
    __stcs(orow0 + 1, r0[1]);
    __stcs(orow0 + 2, r0[2]);
    __stcs(orow0 + 3, r0[3]);
    __stcs(orow1 + 0, r1[0]);
    __stcs(orow1 + 1, r1[1]);
    __stcs(orow1 + 2, r1[2]);
    __stcs(orow1 + 3, r1[3]);
}

extern "C" void kernel_launch(void* const* d_in, const int* in_sizes, int n_in,
                              void* d_out, int out_size) {
    const float* x = (const float*)d_in[0];
    float* out = (float*)d_out;
    const unsigned total = NIMG * S * WO;   // 1,048,576
    haar_recon_kernel<<<total / 256, 256>>>(x, out);
}

// round 4
// speedup vs baseline: 1.0983x; 1.0983x over previous
#include <cuda_runtime.h>

// 2x2 Haar inverse reconstruction:
//   x: (32, 4, 512, 512) f32  ->  out: (32, 1, 1024, 1024) f32
// With a,b,c,d = x[n,0..3,h,w]:
//   L0 = R*a + R*b ; L1 = R*a - R*b
//   H0 = R*c + R*d ; H1 = R*c - R*d
//   out[n,2h,  2w] = R*L0 + R*H0 ; out[n,2h,  2w+1] = R*L0 - R*H0
//   out[n,2h+1,2w] = R*L1 + R*H1 ; out[n,2h+1,2w+1] = R*L1 - R*H1
//
// Touch-once streaming: 128MiB in + 128MiB out. All accesses use .cs
// (evict-first) so the stream passes through L2 instead of thrashing it.
// Each thread: 4x LDG.128.cs, 4x STG.128.cs.  (R2 shape + cache hints.)

#define RCONST 0.70710678118654752440f

static constexpr int S = 512;     // input spatial
static constexpr int NIMG = 32;   // batch
static constexpr int WQ = S / 4;  // float4 chunks per row = 128

__device__ __forceinline__ void haar4(float a, float b, float c, float d,
                                      float& o00, float& o01, float& o10, float& o11) {
    float l0 = RCONST * a + RCONST * b;
    float l1 = RCONST * a - RCONST * b;
    float h0 = RCONST * c + RCONST * d;
    float h1 = RCONST * c - RCONST * d;
    o00 = RCONST * l0 + RCONST * h0;
    o01 = RCONST * l0 - RCONST * h0;
    o10 = RCONST * l1 + RCONST * h1;
    o11 = RCONST * l1 - RCONST * h1;
}

__global__ __launch_bounds__(256)
void haar_recon_kernel(const float* __restrict__ x, float* __restrict__ out) {
    // tid layout: [n:5][h:9][wq:7]   total = 32*512*128 = 2,097,152 threads
    unsigned tid = blockIdx.x * 256u + threadIdx.x;
    unsigned wq = tid & (WQ - 1);
    unsigned h  = (tid >> 7) & (S - 1);
    unsigned n  = tid >> 16;

    const size_t cs4 = (size_t)S * S / 4;   // channel stride in float4 units
    const float4* base = (const float4*)(x + (size_t)n * 4 * S * S + (size_t)h * S) + wq;

    // 4 independent 128-bit streaming loads (MLP=4), evict-first in L2
    float4 a = __ldcs(base);
    float4 b = __ldcs(base + cs4);
    float4 c = __ldcs(base + 2 * cs4);
    float4 d = __ldcs(base + 3 * cs4);

    float4 r0a, r0b, r1a, r1b;
    haar4(a.x, b.x, c.x, d.x, r0a.x, r0a.y, r1a.x, r1a.y);
    haar4(a.y, b.y, c.y, d.y, r0a.z, r0a.w, r1a.z, r1a.w);
    haar4(a.z, b.z, c.z, d.z, r0b.x, r0b.y, r1b.x, r1b.y);
    haar4(a.w, b.w, c.w, d.w, r0b.z, r0b.w, r1b.z, r1b.w);

    // output: (n, 2S, 2S); rows 2h and 2h+1, cols [8*wq, 8*wq+8)
    float4* orow0 = (float4*)(out + ((size_t)n * 2 * S + 2 * h) * (2 * S)) + 2 * wq;
    float4* orow1 = orow0 + (2 * S) / 4;   // next row

    __stcs(orow0 + 0, r0a);
    __stcs(orow0 + 1, r0b);
    __stcs(orow1 + 0, r1a);
    __stcs(orow1 + 1, r1b);
}

extern "C" void kernel_launch(void* const* d_in, const int* in_sizes, int n_in,
                              void* d_out, int out_size) {
    const float* x = (const float*)d_in[0];
    float* out = (float*)d_out;
    const unsigned total = NIMG * S * WQ;   // 2,097,152
    haar_recon_kernel<<<total / 256, 256>>>(x, out);
}

// round 5
// speedup vs baseline: 1.1620x; 1.0580x over previous
#include <cuda_runtime.h>
#include <cstdint>

// 2x2 Haar inverse reconstruction:
//   x: (32, 4, 512, 512) f32  ->  out: (32, 1, 1024, 1024) f32
//   L0 = R*a + R*b ; L1 = R*a - R*b ; H0 = R*c + R*d ; H1 = R*c - R*d
//   out[2h,2w]=R*L0+R*H0  out[2h,2w+1]=R*L0-R*H0
//   out[2h+1,2w]=R*L1+R*H1  out[2h+1,2w+1]=R*L1-R*H1
//
// R5: loads unchanged (4x LDG.128.cs / thread). Output staged in smem
// (one CTA = 2 input rows -> 4 contiguous output rows = 16KB), written
// with a single cp.async.bulk (bulk-group) per CTA: large contiguous DRAM
// write bursts instead of interleaved per-warp STGs.

#define RCONST 0.70710678118654752440f

static constexpr int S = 512;     // input spatial
static constexpr int NIMG = 32;   // batch

__device__ __forceinline__ void haar4(float a, float b, float c, float d,
                                      float& o00, float& o01, float& o10, float& o11) {
    float l0 = RCONST * a + RCONST * b;
    float l1 = RCONST * a - RCONST * b;
    float h0 = RCONST * c + RCONST * d;
    float h1 = RCONST * c - RCONST * d;
    o00 = RCONST * l0 + RCONST * h0;
    o01 = RCONST * l0 - RCONST * h0;
    o10 = RCONST * l1 + RCONST * h1;
    o11 = RCONST * l1 - RCONST * h1;
}

__device__ __forceinline__ uint32_t smem_u32(const void* p) {
    uint32_t a;
    asm("{ .reg .u64 t; cvta.to.shared.u64 t, %1; cvt.u32.u64 %0, t; }"
        : "=r"(a) : "l"(p));
    return a;
}

__global__ __launch_bounds__(256)
void haar_recon_kernel(const float* __restrict__ x, float* __restrict__ out) {
    __shared__ float stage[4 * 2 * S];   // 4 output rows x 1024 floats = 16KB

    unsigned t  = threadIdx.x;
    unsigned b  = blockIdx.x;
    unsigned wq = t & 127;        // float4 index within input row
    unsigned hl = t >> 7;         // 0/1: which of the 2 input rows
    unsigned k  = b & 255;        // input row-pair index (h = 2k+hl)
    unsigned n  = b >> 8;         // image
    unsigned h  = 2 * k + hl;

    const size_t cs4 = (size_t)S * S / 4;   // channel stride in float4
    const float4* base = (const float4*)(x + (size_t)n * 4 * S * S + (size_t)h * S) + wq;

    // 4 independent 128-bit streaming loads (MLP=4)
    float4 a  = __ldcs(base);
    float4 bb = __ldcs(base + cs4);
    float4 c  = __ldcs(base + 2 * cs4);
    float4 d  = __ldcs(base + 3 * cs4);

    float4 r0a, r0b, r1a, r1b;
    haar4(a.x, bb.x, c.x, d.x, r0a.x, r0a.y, r1a.x, r1a.y);
    haar4(a.y, bb.y, c.y, d.y, r0a.z, r0a.w, r1a.z, r1a.w);
    haar4(a.z, bb.z, c.z, d.z, r0b.x, r0b.y, r1b.x, r1b.y);
    haar4(a.w, bb.w, c.w, d.w, r0b.z, r0b.w, r1b.z, r1b.w);

    // stage rows: local rows (2*hl, 2*hl+1), cols [8wq, 8wq+8)
    float4* srow0 = (float4*)(stage + (2 * hl)     * (2 * S)) + 2 * wq;
    float4* srow1 = (float4*)(stage + (2 * hl + 1) * (2 * S)) + 2 * wq;
    srow0[0] = r0a;
    srow0[1] = r0b;
    srow1[0] = r1a;
    srow1[1] = r1b;

    __syncthreads();

    if (t == 0) {
        // make generic-proxy smem stores visible to the async proxy
        asm volatile("fence.proxy.async.shared::cta;" ::: "memory");
        float* gdst = out + ((size_t)n * 2 * S + (size_t)4 * k) * (2 * S);
        uint32_t s = smem_u32(stage);
        asm volatile(
            "cp.async.bulk.global.shared::cta.bulk_group [%0], [%1], %2;"
            :: "l"(gdst), "r"(s), "r"((unsigned)(4 * 2 * S * sizeof(float)))
            : "memory");
        asm volatile("cp.async.bulk.commit_group;" ::: "memory");
        asm volatile("cp.async.bulk.wait_group 0;" ::: "memory");
    }
}

extern "C" void kernel_launch(void* const* d_in, const int* in_sizes, int n_in,
                              void* d_out, int out_size) {
    const float* x = (const float*)d_in[0];
    float* out = (float*)d_out;
    // one CTA per (n, input-row-pair): 32 * 256 = 8192 CTAs
    haar_recon_kernel<<<NIMG * (S / 2), 256>>>(x, out);
}

// round 6
// speedup vs baseline: 1.1652x; 1.0028x over previous
#include <cuda_runtime.h>
#include <cstdint>

// 2x2 Haar inverse reconstruction:
//   x: (32, 4, 512, 512) f32  ->  out: (32, 1, 1024, 1024) f32
//   L0=R*a+R*b; L1=R*a-R*b; H0=R*c+R*d; H1=R*c-R*d
//   out[2h,2w]=R*(L0+H0)  out[2h,2w+1]=R*(L0-H0)
//   out[2h+1,2w]=R*(L1+H1)  out[2h+1,2w+1]=R*(L1-H1)
//
// R6: ALL DRAM traffic via cp.async.bulk.
//   in : per CTA, 4 bulk loads of 4KB (rows 2k,2k+1 of each channel) -> smem
//   out: one bulk store of 16KB (4 contiguous output rows)
// LSU only touches smem; async engine sees >=4KB contiguous bursts both ways.

#define RCONST 0.70710678118654752440f

static constexpr int S = 512;     // input spatial
static constexpr int NIMG = 32;   // batch

__device__ __forceinline__ void haar4(float a, float b, float c, float d,
                                      float& o00, float& o01, float& o10, float& o11) {
    float l0 = RCONST * a + RCONST * b;
    float l1 = RCONST * a - RCONST * b;
    float h0 = RCONST * c + RCONST * d;
    float h1 = RCONST * c - RCONST * d;
    o00 = RCONST * l0 + RCONST * h0;
    o01 = RCONST * l0 - RCONST * h0;
    o10 = RCONST * l1 + RCONST * h1;
    o11 = RCONST * l1 - RCONST * h1;
}

__device__ __forceinline__ uint32_t smem_u32(const void* p) {
    uint32_t a;
    asm("{ .reg .u64 t; cvta.to.shared.u64 t, %1; cvt.u32.u64 %0, t; }"
        : "=r"(a) : "l"(p));
    return a;
}

__global__ __launch_bounds__(256)
void haar_recon_kernel(const float* __restrict__ x, float* __restrict__ out) {
    // in: [channel][local row 0/1][512 floats] = 16KB
    __shared__ alignas(16) float sin[4][2][S];
    // out: 4 output rows x 1024 floats = 16KB
    __shared__ alignas(16) float sout[4 * 2 * S];
    __shared__ alignas(8) uint64_t mbar;

    unsigned t  = threadIdx.x;
    unsigned b  = blockIdx.x;
    unsigned wq = t & 127;        // float4 index within input row
    unsigned hl = t >> 7;         // 0/1: which of the 2 input rows
    unsigned k  = b & 255;        // input row-pair index (h = 2k+hl)
    unsigned n  = b >> 8;         // image

    if (t == 0) {
        asm volatile("mbarrier.init.shared.b64 [%0], 1;"
                     :: "r"(smem_u32(&mbar)) : "memory");
        asm volatile("fence.proxy.async.shared::cta;" ::: "memory");
    }
    __syncthreads();

    if (t == 0) {
        uint32_t mb = smem_u32(&mbar);
        asm volatile("mbarrier.arrive.expect_tx.shared.b64 _, [%0], %1;"
                     :: "r"(mb), "r"(4u * 2u * S * (unsigned)sizeof(float)) : "memory");
        const float* src = x + (size_t)n * 4 * S * S + (size_t)(2 * k) * S;
        #pragma unroll
        for (int ch = 0; ch < 4; ch++) {
            asm volatile(
                "cp.async.bulk.shared::cta.global.mbarrier::complete_tx::bytes "
                "[%0], [%1], %2, [%3];"
                :: "r"(smem_u32(&sin[ch][0][0])),
                   "l"(src + (size_t)ch * S * S),
                   "r"(2u * S * (unsigned)sizeof(float)),   // 4KB: rows 2k,2k+1
                   "r"(mb)
                : "memory");
        }
    }

    // wait for all 16KB to land (phase 0)
    {
        uint32_t mb = smem_u32(&mbar);
        asm volatile(
            "{\n\t"
            ".reg .pred P;\n\t"
            "WL_%=:\n\t"
            "mbarrier.try_wait.parity.shared.b64 P, [%0], 0, 0x989680;\n\t"
            "@P bra.uni WD_%=;\n\t"
            "bra.uni WL_%=;\n\t"
            "WD_%=:\n\t"
            "}"
            :: "r"(mb) : "memory");
    }

    // compute from smem
    const float4* pa = (const float4*)&sin[0][hl][0] + wq;
    const float4* pb = (const float4*)&sin[1][hl][0] + wq;
    const float4* pc = (const float4*)&sin[2][hl][0] + wq;
    const float4* pd = (const float4*)&sin[3][hl][0] + wq;
    float4 a  = *pa;
    float4 bb = *pb;
    float4 c  = *pc;
    float4 d  = *pd;

    float4 r0a, r0b, r1a, r1b;
    haar4(a.x, bb.x, c.x, d.x, r0a.x, r0a.y, r1a.x, r1a.y);
    haar4(a.y, bb.y, c.y, d.y, r0a.z, r0a.w, r1a.z, r1a.w);
    haar4(a.z, bb.z, c.z, d.z, r0b.x, r0b.y, r1b.x, r1b.y);
    haar4(a.w, bb.w, c.w, d.w, r0b.z, r0b.w, r1b.z, r1b.w);

    float4* srow0 = (float4*)(sout + (2 * hl)     * (2 * S)) + 2 * wq;
    float4* srow1 = (float4*)(sout + (2 * hl + 1) * (2 * S)) + 2 * wq;
    srow0[0] = r0a;
    srow0[1] = r0b;
    srow1[0] = r1a;
    srow1[1] = r1b;

    __syncthreads();

    if (t == 0) {
        asm volatile("fence.proxy.async.shared::cta;" ::: "memory");
        float* gdst = out + ((size_t)n * 2 * S + (size_t)4 * k) * (2 * S);
        asm volatile(
            "cp.async.bulk.global.shared::cta.bulk_group [%0], [%1], %2;"
            :: "l"(gdst), "r"(smem_u32(sout)),
               "r"((unsigned)(4 * 2 * S * sizeof(float)))
            : "memory");
        asm volatile("cp.async.bulk.commit_group;" ::: "memory");
        asm volatile("cp.async.bulk.wait_group 0;" ::: "memory");
    }
}

extern "C" void kernel_launch(void* const* d_in, const int* in_sizes, int n_in,
                              void* d_out, int out_size) {
    const float* x = (const float*)d_in[0];
    float* out = (float*)d_out;
    // one CTA per (n, input-row-pair): 32 * 256 = 8192 CTAs
    haar_recon_kernel<<<NIMG * (S / 2), 256>>>(x, out);
}